// round 9
// baseline (speedup 1.0000x reference)
#include <cuda_runtime.h>
#include <cuda_bf16.h>

// loss = -(1/B) * sum_b [ 1 / (sum_j sigmoid(x[b,j] - x[b,0]) + 0.5) ]
// B = 32, N = 2048. Only row i=0 of the reference's [B,N,N] pair matrix is
// used, so compute the O(B*N) reduction directly.
//
// Single-launch, single-atomic tail:
//  - each of 32 blocks reduces one row to a partial part = -rr/32,
//  - the partial is encoded as fixed point (2^45 scale, +2^40 bias so it is
//    non-negative) in the low 46 bits, with an arrival count in bits [46..),
//    and accumulated with ONE relaxed atomicAdd(u64). The winner (old count
//    == 31) gets the full sum from the atomic's RETURN VALUE — no release
//    red, no acquire load, no fences.
//  - winner decodes (exact in double), writes out[0], resets g_acc to 0 so
//    device state is identical after every launch (graph-replay safe).
//    Integer accumulation commutes exactly -> bit-deterministic output.

#define RB 32  // batch count (grid size)

static __device__ unsigned long long g_acc = 0ULL;

// Fixed-point layout: bits [0,46) sum field, bits [46,..) arrival counter.
#define SUM_SHIFT 46
#define SUM_MASK  ((1ULL << SUM_SHIFT) - 1ULL)
#define FP_SCALE  35184372088832.0f   /* 2^45 */
#define FP_BIAS   (1LL << 40)         /* part >= -1/32 -> part*2^45 >= -2^40 */

static __global__ void __launch_bounds__(128) rankloss_fused_kernel(
    const float* __restrict__ x, float* __restrict__ out, float inv_B)
{
    const int b   = blockIdx.x;
    const int tid = threadIdx.x;
    const float* row = x + (size_t)b * 2048;

    const float x0 = __ldg(row);

    // 2048 floats = 512 float4; 128 threads -> 4 loads each, front-batched
    // (MLP=4) so DRAM latencies overlap.
    const float4* row4 = reinterpret_cast<const float4*>(row);
    float4 v0 = __ldg(row4 + tid);
    float4 v1 = __ldg(row4 + tid + 128);
    float4 v2 = __ldg(row4 + tid + 256);
    float4 v3 = __ldg(row4 + tid + 384);

    // sigmoid(v - x0) = 1 / (1 + exp(x0 - v))
    float s = 0.0f;
    s += __fdividef(1.0f, 1.0f + __expf(x0 - v0.x));
    s += __fdividef(1.0f, 1.0f + __expf(x0 - v0.y));
    s += __fdividef(1.0f, 1.0f + __expf(x0 - v0.z));
    s += __fdividef(1.0f, 1.0f + __expf(x0 - v0.w));
    s += __fdividef(1.0f, 1.0f + __expf(x0 - v1.x));
    s += __fdividef(1.0f, 1.0f + __expf(x0 - v1.y));
    s += __fdividef(1.0f, 1.0f + __expf(x0 - v1.z));
    s += __fdividef(1.0f, 1.0f + __expf(x0 - v1.w));
    s += __fdividef(1.0f, 1.0f + __expf(x0 - v2.x));
    s += __fdividef(1.0f, 1.0f + __expf(x0 - v2.y));
    s += __fdividef(1.0f, 1.0f + __expf(x0 - v2.z));
    s += __fdividef(1.0f, 1.0f + __expf(x0 - v2.w));
    s += __fdividef(1.0f, 1.0f + __expf(x0 - v3.x));
    s += __fdividef(1.0f, 1.0f + __expf(x0 - v3.y));
    s += __fdividef(1.0f, 1.0f + __expf(x0 - v3.z));
    s += __fdividef(1.0f, 1.0f + __expf(x0 - v3.w));

    // warp reduce
    #pragma unroll
    for (int o = 16; o > 0; o >>= 1)
        s += __shfl_xor_sync(0xFFFFFFFFu, s, o);

    __shared__ float warp_sums[4];
    const int warp = tid >> 5;
    const int lane = tid & 31;
    if (lane == 0) warp_sums[warp] = s;
    __syncthreads();

    if (tid == 0) {
        float t = warp_sums[0] + warp_sums[1] + warp_sums[2] + warp_sums[3];
        // t >= 0.5 (self term sigmoid(0)=0.5) -> rr = 1/(t+0.5) in (0, 1]
        // part = -rr/32 in [-1/32, 0)
        float part = -(1.0f / (t + 0.5f)) * inv_B;

        // Fixed-point encode: exact power-of-two scaling, rn convert, int bias.
        long long q = __float2ll_rn(part * FP_SCALE) + FP_BIAS;  // [0, 2^40]
        unsigned long long contrib =
            (1ULL << SUM_SHIFT) | (unsigned long long)q;

        // One relaxed atomic carries BOTH the data and the arrival count.
        unsigned long long old = atomicAdd(&g_acc, contrib);

        if ((old >> SUM_SHIFT) == (unsigned long long)(RB - 1)) {
            // Winner: full sum = previously accumulated field + my q.
            long long sum_q =
                (long long)((old & SUM_MASK) + (unsigned long long)q);
            // Undo the 32 biases, rescale (exact in double).
            double total = (double)(sum_q - (long long)RB * FP_BIAS)
                         * (1.0 / 35184372088832.0);  // * 2^-45
            out[0] = (float)total;
            // Reset for next replay; all blocks have arrived, no race.
            asm volatile("st.relaxed.gpu.global.u64 [%0], %1;"
                         :: "l"(&g_acc), "l"(0ULL) : "memory");
        }
    }
}

extern "C" void kernel_launch(void* const* d_in, const int* in_sizes, int n_in,
                              void* d_out, int out_size) {
    const float* x = (const float*)d_in[0];
    float* out = (float*)d_out;

    const int total = in_sizes[0];   // B * N = 65536
    const int N = 2048;
    const int B = total / N;         // 32 == RB

    rankloss_fused_kernel<<<B, 128>>>(x, out, 1.0f / (float)B);
}

// round 11
// speedup vs baseline: 1.0628x; 1.0628x over previous
#include <cuda_runtime.h>
#include <cuda_bf16.h>

// loss = -(1/B) * sum_b [ 1 / (sum_j sigmoid(x[b,j] - x[b,0]) + 0.5) ]
// B = 32, N = 2048. Only row i=0 of the reference's [B,N,N] pair matrix is
// used, so compute the O(B*N) reduction directly.
//
// Single launch, integer end-to-end reduction, packed atomics at both levels:
//  - 32 blocks x 256 threads; 2 front-batched float4 loads per thread.
//  - per-thread sigmoid sum quantized to fixed point (2^22); warp reduce via
//    redux.sync.add.s32 (__reduce_add_sync, sm_80+ — redux.f32 is NOT legal
//    on sm_103 plain target, learned in R10).
//  - block combine: each warp's lane 0 adds (1<<48)|warp_sum into a shared
//    u64; the 8th arriver (count==7 in the RETURN value) owns the block
//    total. No __syncthreads after the work, no smem array walk.
//  - global combine: block partial part = -rr/32 encoded fixed-point
//    (2^45 scale, +2^40 bias) in low 46 bits of g_acc, arrival count at bit
//    46. ONE relaxed atomicAdd(u64); winner (count==31) reads the final sum
//    from the return value, writes out[0], resets g_acc -> device state is 0
//    after every launch (graph-replay safe) and output is bit-deterministic.

#define RB 32  // batch count (grid size)

static __device__ unsigned long long g_acc = 0ULL;

// Global packing: bits [0,46) sum field, bits [46,..) arrival counter.
#define SUM_SHIFT 46
#define SUM_MASK  ((1ULL << SUM_SHIFT) - 1ULL)
#define FP_SCALE  35184372088832.0f   /* 2^45 */
#define FP_INV    (1.0 / 35184372088832.0)
#define FP_BIAS   (1LL << 40)         /* part >= -1/32 -> part*2^45 >= -2^40 */

// Block packing: bits [0,48) int row sum (<= 2^33), count at bit 48.
#define BLK_SHIFT 48
#define BLK_MASK  ((1ULL << BLK_SHIFT) - 1ULL)
#define TQ_SCALE  4194304.0f          /* 2^22 */
#define TQ_INV    (1.0f / 4194304.0f)

static __global__ void __launch_bounds__(256) rankloss_fused_kernel(
    const float* __restrict__ x, float* __restrict__ out, float inv_B)
{
    __shared__ unsigned long long blk_acc;
    const int tid = threadIdx.x;
    if (tid == 0) blk_acc = 0ULL;
    __syncthreads();  // top-of-kernel: warps are near-synchronous here, cheap

    const int b = blockIdx.x;
    const float* row = x + (size_t)b * 2048;

    const float x0 = __ldg(row);

    // 2048 floats = 512 float4; 256 threads -> 2 loads each, front-batched.
    const float4* row4 = reinterpret_cast<const float4*>(row);
    float4 v0 = __ldg(row4 + tid);
    float4 v1 = __ldg(row4 + tid + 256);

    // sigmoid(v - x0) = 1 / (1 + exp(x0 - v))
    float s = 0.0f;
    s += __fdividef(1.0f, 1.0f + __expf(x0 - v0.x));
    s += __fdividef(1.0f, 1.0f + __expf(x0 - v0.y));
    s += __fdividef(1.0f, 1.0f + __expf(x0 - v0.z));
    s += __fdividef(1.0f, 1.0f + __expf(x0 - v0.w));
    s += __fdividef(1.0f, 1.0f + __expf(x0 - v1.x));
    s += __fdividef(1.0f, 1.0f + __expf(x0 - v1.y));
    s += __fdividef(1.0f, 1.0f + __expf(x0 - v1.z));
    s += __fdividef(1.0f, 1.0f + __expf(x0 - v1.w));

    // Quantize (s in (0,8), so si <= 2^25; warp sum <= 2^30, no overflow),
    // then ONE-instruction warp reduction (redux.sync.add.s32, sm_80+).
    int si = __float2int_rn(s * TQ_SCALE);
    int w  = __reduce_add_sync(0xFFFFFFFFu, si);

    if ((tid & 31) == 0) {
        // Block-level packed atomic: data + arrival count in one ATOMS.
        unsigned long long bc =
            (1ULL << BLK_SHIFT) | (unsigned long long)(unsigned int)w;
        unsigned long long bold = atomicAdd(&blk_acc, bc);

        if ((bold >> BLK_SHIFT) == 7ULL) {  // 8 warps per block
            long long ti =
                (long long)((bold & BLK_MASK) + (unsigned long long)(unsigned int)w);
            float t = (float)ti * TQ_INV;           // row sum (exact int, ~2^-24 rel cvt err)
            float part = -(1.0f / (t + 0.5f)) * inv_B;  // in [-1/32, 0)

            // Global packed atomic (R9 scheme).
            long long q = __float2ll_rn(part * FP_SCALE) + FP_BIAS;  // [0, 2^40]
            unsigned long long contrib =
                (1ULL << SUM_SHIFT) | (unsigned long long)q;
            unsigned long long old = atomicAdd(&g_acc, contrib);

            if ((old >> SUM_SHIFT) == (unsigned long long)(RB - 1)) {
                long long sum_q =
                    (long long)((old & SUM_MASK) + (unsigned long long)q);
                double total =
                    (double)(sum_q - (long long)RB * FP_BIAS) * FP_INV;
                out[0] = (float)total;
                // Reset for next replay; all blocks arrived, no race.
                asm volatile("st.relaxed.gpu.global.u64 [%0], %1;"
                             :: "l"(&g_acc), "l"(0ULL) : "memory");
            }
        }
    }
}

extern "C" void kernel_launch(void* const* d_in, const int* in_sizes, int n_in,
                              void* d_out, int out_size) {
    const float* x = (const float*)d_in[0];
    float* out = (float*)d_out;

    const int total = in_sizes[0];   // B * N = 65536
    const int N = 2048;
    const int B = total / N;         // 32 == RB

    rankloss_fused_kernel<<<B, 256>>>(x, out, 1.0f / (float)B);
}